// round 13
// baseline (speedup 1.0000x reference)
#include <cuda_runtime.h>
#include <cuda_bf16.h>
#include <math.h>

// Problem constants
#define B_   32
#define H_   32
#define KV_  8
#define G_   4      // H/KV
#define S_   4096
#define D_   64
#define HID_ 2048
#define FF_  8192
#define V_   32000
#define NSPLIT 16
#define SC_  (S_/NSPLIT)   // 256

// ---------------- scratch (device global; no allocation allowed) -------------
#define OFF_CTX   0
#define OFF_H1    (OFF_CTX + B_*HID_)
#define OFF_X2    (OFF_H1 + B_*HID_)
#define OFF_FF    (OFF_X2 + B_*HID_)
#define OFF_H3    (OFF_FF + B_*FF_)
#define OFF_XF    (OFF_H3 + B_*HID_)
#define OFF_OPART (OFF_XF + B_*HID_)
#define OFF_ML    (OFF_OPART + B_*KV_*G_*NSPLIT*D_)
#define OFF_PART  (OFF_ML + B_*KV_*G_*NSPLIT*2)
#define SCRATCH_TOTAL (OFF_PART + 16*B_*FF_)

__device__ float g_scratch[SCRATCH_TOTAL];

// =============================================================================
// warp-MMA helpers (plain sm_103-legal: HMMA via mma.sync + ldmatrix)
// =============================================================================
__device__ __forceinline__ unsigned s2u(const void* p) {
    return (unsigned)__cvta_generic_to_shared(p);
}
__device__ __forceinline__ void ldm4(unsigned* r, unsigned addr) {
    asm volatile("ldmatrix.sync.aligned.m8n8.x4.shared.b16 {%0,%1,%2,%3}, [%4];"
                 : "=r"(r[0]), "=r"(r[1]), "=r"(r[2]), "=r"(r[3]) : "r"(addr));
}
__device__ __forceinline__ void mma16816(float* d, const unsigned* a,
                                         const unsigned* b) {
    asm volatile(
        "mma.sync.aligned.m16n8k16.row.col.f32.bf16.bf16.f32 "
        "{%0,%1,%2,%3}, {%4,%5,%6,%7}, {%8,%9}, {%0,%1,%2,%3};"
        : "+f"(d[0]), "+f"(d[1]), "+f"(d[2]), "+f"(d[3])
        : "r"(a[0]), "r"(a[1]), "r"(a[2]), "r"(a[3]), "r"(b[0]), "r"(b[1]));
}

// Swizzled smem byte offset: 64B rows, 16B chunks, chunk ^= (row>>1)&3.
// Always 16B-aligned for chunk-granularity accesses; conflict-free ldmatrix.
__device__ __forceinline__ unsigned swz(int row, int chunk) {
    return (unsigned)(row * 64 + ((chunk ^ ((row >> 1) & 3)) << 4));
}

// =============================================================================
// Kernel 1: flash-decode attention partials. grid (NSPLIT, KV, B), 256 thr.
// =============================================================================
__global__ __launch_bounds__(256)
void attn_partial(const float* __restrict__ q, const float* __restrict__ ks,
                  const float* __restrict__ vs,
                  float* __restrict__ opart, float* __restrict__ ml) {
    const int split = blockIdx.x, kv = blockIdx.y, b = blockIdx.z;
    const int tid = threadIdx.x;

    __shared__ float4 qs4[G_][16];
    __shared__ float  sc[G_][SC_];
    __shared__ float  red[256];
    __shared__ float  ms[G_], ls[G_];
    __shared__ float4 pc[4][G_][16];

    {
        int g = tid >> 6, kk = tid & 63;
        reinterpret_cast<float*>(qs4)[tid] =
            q[((size_t)b * H_ + kv * G_ + g) * D_ + kk];
    }
    __syncthreads();

    const int s0 = split * SC_;
    {
        const float4* kp = reinterpret_cast<const float4*>(
            ks + (((size_t)b * KV_ + kv) * S_ + s0 + tid) * D_);
        float d0 = 0.f, d1 = 0.f, d2 = 0.f, d3 = 0.f;
#pragma unroll
        for (int k4 = 0; k4 < 16; k4++) {
            float4 kvv = kp[k4];
            float4 q0 = qs4[0][k4], q1 = qs4[1][k4];
            float4 q2 = qs4[2][k4], q3 = qs4[3][k4];
            d0 += kvv.x*q0.x + kvv.y*q0.y + kvv.z*q0.z + kvv.w*q0.w;
            d1 += kvv.x*q1.x + kvv.y*q1.y + kvv.z*q1.z + kvv.w*q1.w;
            d2 += kvv.x*q2.x + kvv.y*q2.y + kvv.z*q2.z + kvv.w*q2.w;
            d3 += kvv.x*q3.x + kvv.y*q3.y + kvv.z*q3.z + kvv.w*q3.w;
        }
        const float scale = 0.125f;
        sc[0][tid] = d0 * scale; sc[1][tid] = d1 * scale;
        sc[2][tid] = d2 * scale; sc[3][tid] = d3 * scale;
    }
    __syncthreads();

    {
        int g = tid >> 6, i = tid & 63;
        float m = -1e30f;
        for (int s = i; s < SC_; s += 64) m = fmaxf(m, sc[g][s]);
        red[tid] = m; __syncthreads();
        for (int off = 32; off > 0; off >>= 1) {
            if (i < off) red[tid] = fmaxf(red[tid], red[tid + off]);
            __syncthreads();
        }
        if (i == 0) ms[g] = red[tid];
        __syncthreads();
        float mg = ms[g];
        float l = 0.f;
        for (int s = i; s < SC_; s += 64) {
            float p = __expf(sc[g][s] - mg);
            sc[g][s] = p;
            l += p;
        }
        red[tid] = l; __syncthreads();
        for (int off = 32; off > 0; off >>= 1) {
            if (i < off) red[tid] += red[tid + off];
            __syncthreads();
        }
        if (i == 0) ls[g] = red[tid];
    }
    __syncthreads();

    {
        int sg = tid >> 6, g = (tid >> 4) & 3, d4 = tid & 15;
        const float4* vp = reinterpret_cast<const float4*>(
            vs + (((size_t)b * KV_ + kv) * S_ + s0) * D_);
        float4 acc = make_float4(0.f, 0.f, 0.f, 0.f);
        for (int s = sg; s < SC_; s += 4) {
            float p = sc[g][s];
            float4 v4 = vp[s * 16 + d4];
            acc.x += p * v4.x; acc.y += p * v4.y;
            acc.z += p * v4.z; acc.w += p * v4.w;
        }
        pc[sg][g][d4] = acc;
    }
    __syncthreads();

    if (tid < 64) {
        int g = tid >> 4, d4 = tid & 15;
        float4 a = pc[0][g][d4], c1 = pc[1][g][d4];
        float4 c2 = pc[2][g][d4], c3 = pc[3][g][d4];
        float4 o;
        o.x = a.x + c1.x + c2.x + c3.x;
        o.y = a.y + c1.y + c2.y + c3.y;
        o.z = a.z + c1.z + c2.z + c3.z;
        o.w = a.w + c1.w + c2.w + c3.w;
        size_t base = ((((size_t)b * KV_ + kv) * G_ + g) * NSPLIT + split) * (size_t)D_;
        reinterpret_cast<float4*>(opart + base)[d4] = o;
    }
    if (tid < G_) {
        size_t idx = (((size_t)b * KV_ + kv) * G_ + tid) * NSPLIT + split;
        ml[idx * 2]     = ms[tid];
        ml[idx * 2 + 1] = ls[tid];
    }
}

// =============================================================================
// Kernel 2: combine split partials -> ctx [B, H*D]
// =============================================================================
__global__ __launch_bounds__(64)
void attn_combine(const float* __restrict__ opart, const float* __restrict__ ml,
                  float* __restrict__ ctx) {
    int g = blockIdx.x, kv = blockIdx.y, b = blockIdx.z, d = threadIdx.x;
    size_t base = (((size_t)b * KV_ + kv) * G_ + g) * NSPLIT;
    float M = -1e30f;
#pragma unroll
    for (int i = 0; i < NSPLIT; i++) M = fmaxf(M, ml[(base + i) * 2]);
    float L = 0.f, acc = 0.f;
#pragma unroll
    for (int i = 0; i < NSPLIT; i++) {
        float w = __expf(ml[(base + i) * 2] - M);
        L   += ml[(base + i) * 2 + 1] * w;
        acc += opart[(base + i) * D_ + d] * w;
    }
    int h = kv * G_ + g;
    ctx[(size_t)b * HID_ + h * D_ + d] = acc / L;
}

// =============================================================================
// HMMA GEMM v3 (double-buffered, swizzled): out[b,n] = sum_k X[b,k]*W[n,k]
//
// D[M=128 weight rows, N=32 batch] per block. fp32 values LDG'd to regs,
// split to bf16 hi/lo, staged in DOUBLE-BUFFERED smem (64B rows with 16B
// chunk swizzle -> conflict-free AND 16B-aligned ldmatrix; no padding).
// 3 terms: Wh*Xh + Wl*Xh + Wh*Xl, mma.sync m16n8k16 bf16->f32.
// Per-tile: LDG(t+1) -> MMA(t,bufA) -> cvt(t+1,bufB) -> ONE sync.
// MODE 2: direct write. MODE 3: K-split partial. grid (N/128, KSPLIT).
// =============================================================================
#define TGK 32
#define OB_WH 0                        // 128*64 = 8192
#define OB_WL 8192
#define OB_XH 16384                    // 32*64 = 2048
#define OB_XL 18432
#define BUF_BYTES 20480
#define SM_BYTES (2 * BUF_BYTES)       // 40960 < 48KB

template <int MODE>
__global__ __launch_bounds__(256)
void gemm_mma(const float* __restrict__ X, const float* __restrict__ W,
              float* __restrict__ out, int K, int N, int Kc) {
    __shared__ char smem[SM_BYTES];

    const int tid  = threadIdx.x;
    const int warp = tid >> 5;
    const int lane = tid & 31;
    const int nblk = blockIdx.x * 128;
    const int kbeg = blockIdx.y * Kc;
    const int T    = Kc / TGK;

    float acc[4][4];
#pragma unroll
    for (int j = 0; j < 4; j++)
#pragma unroll
        for (int i = 0; i < 4; i++) acc[j][i] = 0.f;

    float4 wreg[4], xreg;

    auto load_tile = [&](int t) {
        const int k0 = kbeg + t * TGK;
#pragma unroll
        for (int r = 0; r < 4; r++) {
            int idx = tid + r * 256;            // 0..1023: row=idx>>3, f4=idx&7
            int row = idx >> 3, f4 = idx & 7;
            wreg[r] = *reinterpret_cast<const float4*>(
                W + (size_t)(nblk + row) * K + k0 + f4 * 4);
        }
        {
            int row = tid >> 3, f4 = tid & 7;   // 32 rows x 8 f4
            xreg = *reinterpret_cast<const float4*>(
                X + (size_t)row * K + k0 + f4 * 4);
        }
    };

    // store one float4's worth (4 fp32 -> 4+4 bf16 = 8B hi + 8B lo)
    auto cvt_store = [&](float4 v, int row, int f4, char* hi, char* lo) {
        __nv_bfloat162 h01 = __float22bfloat162_rn(make_float2(v.x, v.y));
        __nv_bfloat162 h23 = __float22bfloat162_rn(make_float2(v.z, v.w));
        float lx = v.x - __bfloat162float(h01.x);
        float ly = v.y - __bfloat162float(h01.y);
        float lz = v.z - __bfloat162float(h23.x);
        float lw = v.w - __bfloat162float(h23.y);
        __nv_bfloat162 l01 = __float22bfloat162_rn(make_float2(lx, ly));
        __nv_bfloat162 l23 = __float22bfloat162_rn(make_float2(lz, lw));
        // byte-in-row = f4*8 -> chunk = f4>>1, sub-offset = (f4&1)*8
        unsigned byte = swz(row, f4 >> 1) + (unsigned)((f4 & 1) * 8);
        unsigned long long hv =
            ((unsigned long long)*reinterpret_cast<unsigned*>(&h23) << 32) |
            *reinterpret_cast<unsigned*>(&h01);
        unsigned long long lv =
            ((unsigned long long)*reinterpret_cast<unsigned*>(&l23) << 32) |
            *reinterpret_cast<unsigned*>(&l01);
        *reinterpret_cast<unsigned long long*>(hi + byte) = hv;
        *reinterpret_cast<unsigned long long*>(lo + byte) = lv;
    };

    auto cvt_all = [&](char* buf) {
#pragma unroll
        for (int r = 0; r < 4; r++) {
            int idx = tid + r * 256;
            cvt_store(wreg[r], idx >> 3, idx & 7, buf + OB_WH, buf + OB_WL);
        }
        cvt_store(xreg, tid >> 3, tid & 7, buf + OB_XH, buf + OB_XL);
    };

    // ldmatrix fragment rows/cols (per-warp constants)
    const int arow = warp * 16 + (lane & 15);
    const int ak   = (lane >> 4) << 3;             // element col 0 or 8
    const int brow = (lane & 7) + ((lane >> 4) << 3);
    const int bk   = ((lane >> 3) & 1) << 3;

    auto mma_tile = [&](char* buf) {
#pragma unroll
        for (int k16 = 0; k16 < TGK / 16; k16++) {
            const int kb = k16 * 16;
            unsigned ah[4], al[4], bh[8], bl[8];
            unsigned abyte = swz(arow, (kb + ak) >> 3);
            ldm4(ah, s2u(buf + OB_WH) + abyte);
            ldm4(al, s2u(buf + OB_WL) + abyte);
            unsigned bbyte0 = swz(brow,      (kb + bk) >> 3);
            unsigned bbyte1 = swz(brow + 16, (kb + bk) >> 3);
            ldm4(bh,     s2u(buf + OB_XH) + bbyte0);
            ldm4(bh + 4, s2u(buf + OB_XH) + bbyte1);
            ldm4(bl,     s2u(buf + OB_XL) + bbyte0);
            ldm4(bl + 4, s2u(buf + OB_XL) + bbyte1);
#pragma unroll
            for (int j = 0; j < 4; j++) {
                mma16816(acc[j], ah, bh + j * 2);
                mma16816(acc[j], al, bh + j * 2);
                mma16816(acc[j], ah, bl + j * 2);
            }
        }
    };

    load_tile(0);
    cvt_all(smem);            // buffer 0
    __syncthreads();

    for (int t = 0; t < T; t++) {
        if (t + 1 < T) load_tile(t + 1);       // LDG overlaps MMA below
        mma_tile(smem + (t & 1) * BUF_BYTES);
        if (t + 1 < T) cvt_all(smem + ((t + 1) & 1) * BUF_BYTES);
        __syncthreads();
    }

    // ---- stage acc -> smem [m][b] (pad 33), then coalesced write
    float* stage = reinterpret_cast<float*>(smem);   // 128*33*4 = 16896 B
    {
        int m0 = warp * 16 + (lane >> 2);
        int c0 = (lane & 3) * 2;
#pragma unroll
        for (int j = 0; j < 4; j++) {
            int c = j * 8 + c0;
            stage[m0 * 33 + c]           = acc[j][0];
            stage[m0 * 33 + c + 1]       = acc[j][1];
            stage[(m0 + 8) * 33 + c]     = acc[j][2];
            stage[(m0 + 8) * 33 + c + 1] = acc[j][3];
        }
    }
    __syncthreads();

    {
        int b = tid >> 3;
        size_t row = (MODE == 2) ? (size_t)b : ((size_t)blockIdx.y * B_ + b);
        float* orow = out + row * N + nblk;
#pragma unroll
        for (int r = 0; r < 4; r++) {
            int n4 = (tid & 7) + r * 8;
            float4 v;
            v.x = stage[(n4 * 4 + 0) * 33 + b];
            v.y = stage[(n4 * 4 + 1) * 33 + b];
            v.z = stage[(n4 * 4 + 2) * 33 + b];
            v.w = stage[(n4 * 4 + 3) * 33 + b];
            *reinterpret_cast<float4*>(orow + n4 * 4) = v;
        }
    }
}

// =============================================================================
// Vectorized K-split epilogue.
// MODE 0: +bias+resid   MODE 1: gelu(.+bias)   MODE 2: plain sum
// =============================================================================
template <int MODE, int KS, int N4>
__global__ __launch_bounds__(256)
void epi4(const float* __restrict__ part, const float* __restrict__ bias,
          const float* __restrict__ resid, float* __restrict__ out) {
    int idx = blockIdx.x * 256 + threadIdx.x;
    int b = idx / N4, n = idx % N4;
    const float4* p4 = reinterpret_cast<const float4*>(part);
    float4 v = make_float4(0.f, 0.f, 0.f, 0.f);
#pragma unroll
    for (int ks = 0; ks < KS; ks++) {
        float4 p = p4[(size_t)(ks * B_ + b) * N4 + n];
        v.x += p.x; v.y += p.y; v.z += p.z; v.w += p.w;
    }
    if (MODE == 0) {
        float4 bi = reinterpret_cast<const float4*>(bias)[n];
        float4 rs = reinterpret_cast<const float4*>(resid)[idx];
        v.x += bi.x + rs.x; v.y += bi.y + rs.y;
        v.z += bi.z + rs.z; v.w += bi.w + rs.w;
    } else if (MODE == 1) {
        float4 bi = reinterpret_cast<const float4*>(bias)[n];
        v.x += bi.x; v.y += bi.y; v.z += bi.z; v.w += bi.w;
        const float c = 0.70710678118654752f;
        v.x = 0.5f * v.x * (1.0f + erff(v.x * c));
        v.y = 0.5f * v.y * (1.0f + erff(v.y * c));
        v.z = 0.5f * v.z * (1.0f + erff(v.z * c));
        v.w = 0.5f * v.w * (1.0f + erff(v.w * c));
    }
    reinterpret_cast<float4*>(out)[idx] = v;
}

// =============================================================================
// LayerNorm: grid B, 256 threads, row length 2048.
// =============================================================================
__global__ __launch_bounds__(256)
void ln_kernel(const float* __restrict__ in, const float* __restrict__ gg,
               const float* __restrict__ bb, float* __restrict__ out) {
    int b = blockIdx.x, tid = threadIdx.x;
    __shared__ float red[256];
    const float* row = in + (size_t)b * HID_;
    float v[8];
    float s = 0.f;
#pragma unroll
    for (int i = 0; i < 8; i++) { v[i] = row[tid + i * 256]; s += v[i]; }
    red[tid] = s; __syncthreads();
    for (int off = 128; off > 0; off >>= 1) {
        if (tid < off) red[tid] += red[tid + off];
        __syncthreads();
    }
    float mean = red[0] * (1.0f / HID_);
    __syncthreads();
    float sq = 0.f;
#pragma unroll
    for (int i = 0; i < 8; i++) { float d = v[i] - mean; sq += d * d; }
    red[tid] = sq; __syncthreads();
    for (int off = 128; off > 0; off >>= 1) {
        if (tid < off) red[tid] += red[tid + off];
        __syncthreads();
    }
    float rstd = rsqrtf(red[0] * (1.0f / HID_) + 1e-5f);
#pragma unroll
    for (int i = 0; i < 8; i++) {
        int c = tid + i * 256;
        out[(size_t)b * HID_ + c] = (v[i] - mean) * rstd * gg[c] + bb[c];
    }
}

// =============================================================================
extern "C" void kernel_launch(void* const* d_in, const int* in_sizes, int n_in,
                              void* d_out, int out_size) {
    const float* residual = (const float*)d_in[0];
    const float* q   = (const float*)d_in[1];
    const float* ks  = (const float*)d_in[2];
    const float* vs  = (const float*)d_in[3];
    const float* Wo  = (const float*)d_in[4];
    const float* bo  = (const float*)d_in[5];
    const float* g2  = (const float*)d_in[6];
    const float* b2  = (const float*)d_in[7];
    const float* W1  = (const float*)d_in[8];
    const float* b1  = (const float*)d_in[9];
    const float* W2  = (const float*)d_in[10];
    const float* b2m = (const float*)d_in[11];
    const float* gf  = (const float*)d_in[12];
    const float* bf  = (const float*)d_in[13];
    const float* Wlm = (const float*)d_in[14];
    float* out = (float*)d_out;

    float* scratch = nullptr;
    cudaGetSymbolAddress((void**)&scratch, g_scratch);
    float* ctx   = scratch + OFF_CTX;
    float* h1    = scratch + OFF_H1;
    float* x2    = scratch + OFF_X2;
    float* ff    = scratch + OFF_FF;
    float* h3    = scratch + OFF_H3;
    float* xf    = scratch + OFF_XF;
    float* opart = scratch + OFF_OPART;
    float* ml    = scratch + OFF_ML;
    float* part  = scratch + OFF_PART;

    // 1) attention
    attn_partial<<<dim3(NSPLIT, KV_, B_), 256>>>(q, ks, vs, opart, ml);
    attn_combine<<<dim3(G_, KV_, B_), 64>>>(opart, ml, ctx);

    // 2) Wo projection: 16 n-blocks x 16 K-splits (Kc=128, 4 tiles)
    gemm_mma<3><<<dim3(HID_ / 128, 16), 256>>>(ctx, Wo, part, HID_, HID_, HID_ / 16);
    epi4<0, 16, HID_ / 4><<<(B_ * HID_) / 1024, 256>>>(part, bo, residual, h1);
    ln_kernel<<<B_, 256>>>(h1, g2, b2, x2);

    // 3) FFN up: 64 n-blocks x 4 K-splits (Kc=512, 16 tiles)
    gemm_mma<3><<<dim3(FF_ / 128, 4), 256>>>(x2, W1, part, HID_, FF_, HID_ / 4);
    epi4<1, 4, FF_ / 4><<<(B_ * FF_) / 1024, 256>>>(part, b1, nullptr, ff);

    // 4) FFN down: 16 n-blocks x 16 K-splits (Kc=512, 16 tiles)
    gemm_mma<3><<<dim3(HID_ / 128, 16), 256>>>(ff, W2, part, FF_, HID_, FF_ / 16);
    epi4<0, 16, HID_ / 4><<<(B_ * HID_) / 1024, 256>>>(part, b2m, h1, h3);
    ln_kernel<<<B_, 256>>>(h3, gf, bf, xf);

    // 5) LM head: K-split 2 -> 500 blocks (Kc=1024, 32 tiles), then sum
    gemm_mma<3><<<dim3(V_ / 128, 2), 256>>>(xf, Wlm, part, HID_, V_, HID_ / 2);
    epi4<2, 2, V_ / 4><<<(B_ * V_) / 1024, 256>>>(part, nullptr, nullptr, out);
}